// round 9
// baseline (speedup 1.0000x reference)
#include <cuda_runtime.h>
#include <math.h>

#define B_    32
#define L_    64
#define D_    768
#define LL_   (L_*L_)     // 4096
#define OUTD_ (2*D_)      // 1536

#define TBLK_ 296                 // stageT blocks (2 per SM, single wave)
#define TWARPS_ (TBLK_ * 8)       // 2368 warps; each handles up to 2 of 4096 rows

// scratch
__device__ float g_pooled[B_ * D_];
__device__ float g_t[B_ * 2 * L_];   // t1 (64) then t2 (64) per batch

// ---------------------------------------------------------------------------
// T: t[b, r] = dot(row, we_w) for 4096 (batch,row) tasks.
// grid = 296, block = 256 (8 warps). Warp handles tasks w and w+2368 with all
// 12 float4 loads issued before either reduction (single latency exposure).
// Afterwards, threads prefetch fc_w into L2 for stageB.
// ---------------------------------------------------------------------------
__global__ __launch_bounds__(256) void stageT(
    const float* __restrict__ a1, const float* __restrict__ a2,
    const float* __restrict__ we_w, const float* __restrict__ fc_w)
{
    __shared__ float sw[D_];
    const int tid  = threadIdx.x;
    const int lane = tid & 31;
    const int wid  = tid >> 5;
    const int w    = blockIdx.x * 8 + wid;     // 0..2367

    for (int i = tid; i < D_; i += 256) sw[i] = we_w[i];
    __syncthreads();

    const int tA = w;                 // always valid (< 4096)
    const int tB = w + TWARPS_;       // valid iff < 4096
    const bool hasB = (tB < B_ * 2 * L_);

    const int bA = tA >> 7, rA = tA & 127;
    const float4* rowA = (rA < L_)
        ? ((const float4*)(a1 + (size_t)bA * L_ * D_) + rA * (D_/4))
        : ((const float4*)(a2 + (size_t)bA * L_ * D_) + (rA - L_) * (D_/4));

    const int bB = hasB ? (tB >> 7) : 0;
    const int rB = hasB ? (tB & 127) : 0;
    const float4* rowB = hasB
        ? ((rB < L_)
            ? ((const float4*)(a1 + (size_t)bB * L_ * D_) + rB * (D_/4))
            : ((const float4*)(a2 + (size_t)bB * L_ * D_) + (rB - L_) * (D_/4)))
        : rowA;   // harmless duplicate load, result discarded

    // issue all 12 loads, then reduce
    float4 va[6], vb[6];
    #pragma unroll
    for (int k = 0; k < 6; k++) va[k] = rowA[lane + 32*k];
    #pragma unroll
    for (int k = 0; k < 6; k++) vb[k] = rowB[lane + 32*k];

    const float4* swv = (const float4*)sw;
    float sA = 0.f, sB = 0.f;
    #pragma unroll
    for (int k = 0; k < 6; k++) {
        float4 wv = swv[lane + 32*k];
        sA += va[k].x*wv.x + va[k].y*wv.y + va[k].z*wv.z + va[k].w*wv.w;
        sB += vb[k].x*wv.x + vb[k].y*wv.y + vb[k].z*wv.z + vb[k].w*wv.w;
    }
    #pragma unroll
    for (int o = 16; o; o >>= 1) {
        sA += __shfl_xor_sync(0xffffffffu, sA, o);
        sB += __shfl_xor_sync(0xffffffffu, sB, o);
    }
    if (lane == 0) {
        g_t[bA * 2*L_ + rA] = sA;
        if (hasB) g_t[bB * 2*L_ + rB] = sB;
    }

    // prefetch fc_w (4.7MB = 36864 x 128B lines) into L2 for stageB
    {
        int idx = blockIdx.x * 256 + tid;          // 0..75775
        const int nlines = OUTD_ * D_ * 4 / 128;   // 36864
        if (idx < nlines) {
            const char* p = (const char*)fc_w + (size_t)idx * 128;
            asm volatile("prefetch.global.L2 [%0];" :: "l"(p));
        }
    }
}

// ---------------------------------------------------------------------------
// MA2: merged marginals (recomputed redundantly per block) + pooled chunk.
// grid = (6, B_) = 192 blocks, 256 threads.
// ---------------------------------------------------------------------------
__global__ __launch_bounds__(256) void stageMA2(
    const float* __restrict__ a1, const float* __restrict__ a2,
    const int*   __restrict__ m1, const int*   __restrict__ m2)
{
    __shared__ float  t1[L_], t2[L_];
    __shared__ float  rowsh[L_], colsh[L_];
    __shared__ float  ca[L_], cb[L_];
    __shared__ float  red[8];
    __shared__ int    sl1, sl2;
    __shared__ float  smax, sinvd;
    __shared__ float4 partt[8][32];

    const int b    = blockIdx.y;
    const int cc   = blockIdx.x;
    const int tid  = threadIdx.x;
    const int lane = tid & 31;
    const int wid  = tid >> 5;

    if (tid < 2*L_) {
        float v = g_t[b*2*L_ + tid];
        if (tid < L_) t1[tid] = v; else t2[tid - L_] = v;
    }
    if (tid < L_) { rowsh[tid] = 0.f; colsh[tid] = 0.f; }

    if (wid == 0) {
        int s = m1[b*L_ + lane] + m1[b*L_ + lane + 32];
        #pragma unroll
        for (int o = 16; o; o >>= 1) s += __shfl_xor_sync(0xffffffffu, s, o);
        if (lane == 0) sl1 = s - 2;
    } else if (wid == 1) {
        int s = m2[b*L_ + lane] + m2[b*L_ + lane + 32];
        #pragma unroll
        for (int o = 16; o; o >>= 1) s += __shfl_xor_sync(0xffffffffu, s, o);
        if (lane == 0) sl2 = s - 2;
    }
    __syncthreads();

    const int l1 = sl1, l2 = sl2;

    float lmax = -1e7f;
    for (int i = wid; i < l1; i += 8) {
        const float ti = t1[i+1];
        #pragma unroll
        for (int base = 0; base < L_; base += 32) {
            int j = base + lane;
            if (j < l2) {
                float we = ti - t2[j+1];
                float m = (fabsf(we) < 1e-7f) ? -1e7f : we;
                lmax = fmaxf(lmax, m);
            }
        }
    }
    #pragma unroll
    for (int o = 16; o; o >>= 1) lmax = fmaxf(lmax, __shfl_xor_sync(0xffffffffu, lmax, o));
    if (lane == 0) red[wid] = lmax;
    __syncthreads();
    if (tid == 0) {
        float m = red[0];
        #pragma unroll
        for (int i = 1; i < 8; i++) m = fmaxf(m, red[i]);
        smax = m;
    }
    __syncthreads();
    const float mx = smax;

    for (int i = wid; i < l1; i += 8) {
        const float ti = t1[i+1];
        float s = 0.f;
        #pragma unroll
        for (int base = 0; base < L_; base += 32) {
            int j = base + lane;
            if (j < l2) {
                float we = ti - t2[j+1];
                float m = (fabsf(we) < 1e-7f) ? -1e7f : we;
                s += __expf(m - mx);
            }
        }
        #pragma unroll
        for (int o = 16; o; o >>= 1) s += __shfl_xor_sync(0xffffffffu, s, o);
        if (lane == 0) rowsh[i] = s;
    }
    for (int j = wid; j < l2; j += 8) {
        const float tj = t2[j+1];
        float s = 0.f;
        #pragma unroll
        for (int base = 0; base < L_; base += 32) {
            int i = base + lane;
            if (i < l1) {
                float we = t1[i+1] - tj;
                float m = (fabsf(we) < 1e-7f) ? -1e7f : we;
                s += __expf(m - mx);
            }
        }
        #pragma unroll
        for (int o = 16; o; o >>= 1) s += __shfl_xor_sync(0xffffffffu, s, o);
        if (lane == 0) colsh[j] = s;
    }
    __syncthreads();

    if (wid == 0) {
        float s = rowsh[lane] + rowsh[lane + 32];
        #pragma unroll
        for (int o = 16; o; o >>= 1) s += __shfl_xor_sync(0xffffffffu, s, o);
        if (lane == 0) {
            float pad = (float)(LL_ - l1*l2) * __expf(-1e7f - mx);
            sinvd = 1.f / (s + pad);
        }
    }
    __syncthreads();
    const float invd = sinvd;

    if (tid < L_) {
        ca[tid] = (tid >= 1 && tid - 1 < l1) ? rowsh[tid-1] * invd : 0.f;
    } else if (tid < 2*L_) {
        int j = tid - L_;
        cb[j] = (j >= 1 && j - 1 < l2) ? -colsh[j-1] * invd : 0.f;
    }
    __syncthreads();

    const int col = cc*32 + lane;
    const float4* base1v = (const float4*)(a1 + (size_t)b * L_ * D_);
    const float4* base2v = (const float4*)(a2 + (size_t)b * L_ * D_);

    float4 acc = make_float4(0.f, 0.f, 0.f, 0.f);
    #pragma unroll
    for (int k = 0; k < 8; k++) {
        const int r = wid + 8*k;
        const float c1 = ca[r];
        const float c2 = cb[r];
        float4 v1 = base1v[r*(D_/4) + col];
        float4 v2 = base2v[r*(D_/4) + col];
        acc.x += c1*v1.x + c2*v2.x;
        acc.y += c1*v1.y + c2*v2.y;
        acc.z += c1*v1.z + c2*v2.z;
        acc.w += c1*v1.w + c2*v2.w;
    }
    partt[wid][lane] = acc;
    __syncthreads();

    if (tid < 32) {
        float4 s = partt[0][lane];
        #pragma unroll
        for (int k = 1; k < 8; k++) {
            float4 v = partt[k][lane];
            s.x += v.x; s.y += v.y; s.z += v.z; s.w += v.w;
        }
        ((float4*)g_pooled)[b*(D_/4) + col] = s;
    }
}

// ---------------------------------------------------------------------------
// B: out[b,o] = tanh( dot(pooled[b], fc_w[o]) + fc_b[o] )
// grid = 192, block = 512 (16 warps). One 8-row tile per block.
// ---------------------------------------------------------------------------
__global__ __launch_bounds__(512) void stageB(
    const float* __restrict__ fc_w, const float* __restrict__ fc_b,
    float* __restrict__ out)
{
    __shared__ float sB[8 * D_];   // 24 KB

    const int tid  = threadIdx.x;
    const int lane = tid & 31;
    const int wid  = tid >> 5;
    const int o0   = blockIdx.x * 8;
    const int b0   = wid * 2;

    {
        const float4* src = (const float4*)(fc_w + (size_t)o0 * D_);
        float4*       dst = (float4*)sB;
        #pragma unroll
        for (int k = 0; k < 3; k++)
            dst[tid + 512*k] = src[tid + 512*k];
    }

    const float4* poolv = (const float4*)g_pooled;
    float4 p[2][6];
    #pragma unroll
    for (int bb = 0; bb < 2; bb++)
        #pragma unroll
        for (int k = 0; k < 6; k++)
            p[bb][k] = poolv[(b0 + bb)*(D_/4) + lane + 32*k];

    __syncthreads();

    const float4* sBv = (const float4*)sB;
    #pragma unroll
    for (int r = 0; r < 8; r++) {
        const int o = o0 + r;
        float x0 = 0.f, x1 = 0.f;
        #pragma unroll
        for (int k = 0; k < 6; k++) {
            float4 w = sBv[r*(D_/4) + lane + 32*k];
            x0 += w.x*p[0][k].x + w.y*p[0][k].y + w.z*p[0][k].z + w.w*p[0][k].w;
            x1 += w.x*p[1][k].x + w.y*p[1][k].y + w.z*p[1][k].z + w.w*p[1][k].w;
        }
        #pragma unroll
        for (int off = 16; off; off >>= 1) {
            x0 += __shfl_xor_sync(0xffffffffu, x0, off);
            x1 += __shfl_xor_sync(0xffffffffu, x1, off);
        }
        if (lane == 0) {
            const float bias = fc_b[o];
            out[(size_t)(b0+0)*OUTD_ + o] = tanhf(x0 + bias);
            out[(size_t)(b0+1)*OUTD_ + o] = tanhf(x1 + bias);
        }
    }
}

extern "C" void kernel_launch(void* const* d_in, const int* in_sizes, int n_in,
                              void* d_out, int out_size)
{
    const float* a1   = (const float*)d_in[0];  // (B, L, D)
    const float* a2   = (const float*)d_in[1];  // (B, L, D)
    const int*   m1   = (const int*)  d_in[2];  // (B, L)
    const int*   m2   = (const int*)  d_in[3];  // (B, L)
    const float* we_w = (const float*)d_in[4];  // (1, D)
    const float* fc_w = (const float*)d_in[5];  // (2D, D)
    const float* fc_b = (const float*)d_in[6];  // (2D,)
    float* out = (float*)d_out;                 // (B, 2D)

    stageT<<<TBLK_, 256>>>(a1, a2, we_w, fc_w);
    stageMA2<<<dim3(6, B_), 256>>>(a1, a2, m1, m2);
    stageB<<<OUTD_/8, 512>>>(fc_w, fc_b, out);
}